// round 6
// baseline (speedup 1.0000x reference)
#include <cuda_runtime.h>

// Fixed problem constants:
//   x: (4,1,128,2048) f32 ; vals: 16.7M f32 ; rows/cols: 16.7M int32-or-int64 (rows sorted)
//   out: (4,1,512,256) f32 = 524288 elements
#define NNZ_TOTAL   16777216
#define NCOLS       262144      // NS*NC = 2048*128
#define OUT_ELEMS   524288
#define OUT_PLANE   131072      // per-bk output plane (Nz*Nx)
#define TOTAL_WARPS 16384
#define NNZ_PER_WARP (NNZ_TOTAL / TOTAL_WARPS)   // 1024
#define GROUPS       (NNZ_PER_WARP / 32)         // 32

// Scratch: transposed RHS, rhs_t[col] = {x[0,c,s], x[1,c,s], x[2,c,s], x[3,c,s]}, col = s*128 + c
static __device__ float4  g_rhs[NCOLS];          // 4 MB, L2-resident during main kernel
static __device__ unsigned g_stride;             // 2 if indices are int64, 1 if int32

// --- fused prep: dtype probe + zero output + build transposed RHS -------------
__global__ void k_prep(const float* __restrict__ x,
                       const unsigned* __restrict__ rows_u32,
                       float* __restrict__ out) {
    unsigned gid = blockIdx.x * blockDim.x + threadIdx.x;   // < 524288
    if (gid == 0) g_stride = (rows_u32[NNZ_TOTAL - 1] == 0u) ? 2u : 1u;
    out[gid] = 0.0f;                                        // d_out is poisoned 0xAA
    if (gid < NCOLS) {
        unsigned c = gid & 127u;
        unsigned s = gid >> 7;
        unsigned o = c * 2048u + s;
        float4 v;
        v.x = x[o];
        v.y = x[o + 262144u];
        v.z = x[o + 524288u];
        v.w = x[o + 786432u];
        g_rhs[gid] = v;
    }
}

// --- flush one completed row: butterfly reduce + 4 atomics (cold path) ---------
__device__ __forceinline__ void flush_row(unsigned row,
                                          float a0, float a1, float a2, float a3,
                                          unsigned lane,
                                          float* __restrict__ out) {
    #pragma unroll
    for (int d = 16; d > 0; d >>= 1) {
        a0 += __shfl_xor_sync(0xffffffffu, a0, d);
        a1 += __shfl_xor_sync(0xffffffffu, a1, d);
        a2 += __shfl_xor_sync(0xffffffffu, a2, d);
        a3 += __shfl_xor_sync(0xffffffffu, a3, d);
    }
    if (lane < 4u) {
        float s = (lane == 0u) ? a0 : (lane == 1u) ? a1 : (lane == 2u) ? a2 : a3;
        // out layout: bk*131072 + z*256 + x, with row r = x*512 + z
        unsigned o = (row & 511u) * 256u + (row >> 9);
        atomicAdd(out + lane * OUT_PLANE + o, s);
    }
}

// --- process one 32-nnz group (rows sorted within and across groups) -----------
__device__ __forceinline__ void process_group(float v, unsigned row, float4 r,
                                              unsigned& cur_row,
                                              float& a0, float& a1, float& a2, float& a3,
                                              unsigned lane,
                                              float* __restrict__ out) {
    float c0 = v * r.x, c1 = v * r.y, c2 = v * r.z, c3 = v * r.w;
    if (__all_sync(0xffffffffu, row == cur_row)) {           // fast path (75%)
        a0 += c0; a1 += c1; a2 += c2; a3 += c3;
    } else {                                                 // row boundary in group
        unsigned r31 = __shfl_sync(0xffffffffu, row, 31);
        bool mine = (row == cur_row);                        // sorted -> prefix lanes
        if (mine) { a0 += c0; a1 += c1; a2 += c2; a3 += c3; }
        flush_row(cur_row, a0, a1, a2, a3, lane, out);
        if (!mine && row != r31) {
            // row fully contained inside this group (needs <32 nnz): direct atomics
            unsigned o = (row & 511u) * 256u + (row >> 9);
            atomicAdd(out + o,                  c0);
            atomicAdd(out + OUT_PLANE + o,      c1);
            atomicAdd(out + 2u * OUT_PLANE + o, c2);
            atomicAdd(out + 3u * OUT_PLANE + o, c3);
        }
        bool last = (row == r31);                            // suffix lanes: new row
        a0 = last ? c0 : 0.f;
        a1 = last ? c1 : 0.f;
        a2 = last ? c2 : 0.f;
        a3 = last ? c3 : 0.f;
        cur_row = r31;
    }
}

// --- main SpMM ------------------------------------------------------------------
// Two-level software pipeline: column indices loaded TWO groups ahead, rhs
// gathers issued ONE group ahead. This splits the col-load -> gather dependent
// chain (2 x ~240cyc L2 latency) that previously serialized inside one
// iteration window and capped L1 at 75%.
__global__ void __launch_bounds__(256)
k_spmm(const float* __restrict__ vals,
       const unsigned* __restrict__ rows_u32,
       const unsigned* __restrict__ cols_u32,
       float* __restrict__ out) {
    const unsigned warp_id = (blockIdx.x * blockDim.x + threadIdx.x) >> 5;
    const unsigned lane    = threadIdx.x & 31u;
    const unsigned st      = g_stride;          // 1 (int32) or 2 (int64, read low word)
    const unsigned i0      = warp_id * NNZ_PER_WARP + lane;  // element idx, group 0

    // prologue: groups 0 (full) and 1 (col only)
    unsigned colA = cols_u32[st * i0];                 // col, group 0
    unsigned colB = cols_u32[st * (i0 + 32u)];         // col, group 1
    float4   gA   = g_rhs[colA];                       // gather, group 0
    float    vA   = vals[i0];
    unsigned rowA = rows_u32[st * i0];

    unsigned cur_row = __shfl_sync(0xffffffffu, rowA, 0);
    float a0 = 0.f, a1 = 0.f, a2 = 0.f, a3 = 0.f;

    #pragma unroll 1
    for (unsigned g = 0; g < GROUPS - 2u; g += 2u) {
        // -- even sub-iter: load col(g+2); gather(g+1); streams(g+1); process(g)
        unsigned iC   = i0 + (g + 2u) * 32u;
        unsigned colC = cols_u32[st * iC];
        float4   gB   = g_rhs[colB];
        unsigned iB   = i0 + (g + 1u) * 32u;
        float    vB   = vals[iB];
        unsigned rowB = rows_u32[st * iB];
        process_group(vA, rowA, gA, cur_row, a0, a1, a2, a3, lane, out);

        // -- odd sub-iter: load col(g+3); gather(g+2); streams(g+2); process(g+1)
        unsigned iD   = i0 + (g + 3u) * 32u;
        unsigned colD = cols_u32[st * iD];
        float4   gC   = g_rhs[colC];
        float    vC   = vals[iC];
        unsigned rowC = rows_u32[st * iC];
        process_group(vB, rowB, gB, cur_row, a0, a1, a2, a3, lane, out);

        colB = colD; gA = gC; vA = vC; rowA = rowC;
    }

    // epilogue: groups GROUPS-2 (in gA/vA/rowA) and GROUPS-1 (col in colB)
    {
        float4   gB   = g_rhs[colB];
        unsigned iB   = i0 + (GROUPS - 1u) * 32u;
        float    vB   = vals[iB];
        unsigned rowB = rows_u32[st * iB];
        process_group(vA, rowA, gA, cur_row, a0, a1, a2, a3, lane, out);
        process_group(vB, rowB, gB, cur_row, a0, a1, a2, a3, lane, out);
    }
    flush_row(cur_row, a0, a1, a2, a3, lane, out);
}

extern "C" void kernel_launch(void* const* d_in, const int* in_sizes, int n_in,
                              void* d_out, int out_size) {
    const float*    x    = (const float*)d_in[0];
    const float*    vals = (const float*)d_in[1];
    const unsigned* rows = (const unsigned*)d_in[2];
    const unsigned* cols = (const unsigned*)d_in[3];
    float*          out  = (float*)d_out;

    k_prep<<<OUT_ELEMS / 256, 256>>>(x, rows, out);
    k_spmm<<<TOTAL_WARPS * 32 / 256, 256>>>(vals, rows, cols, out);
}